// round 11
// baseline (speedup 1.0000x reference)
#include <cuda_runtime.h>
#include <math.h>
#include <limits.h>

#define BB 4
#define NN 8192
#define NPOINT 409        // int(8192 * 0.05)
#define NSR 20            // repulsion nsample
#define GRID 26
#define NCELL (GRID*GRID*GRID)   // 17576
#define CAPR 24
#define CAPU 48
#define CG 8
#define CGC (CG*CG*CG)    // 512 coarse cells (FPS ordering only)

typedef unsigned long long ull;

// ---------------- device scratch (no allocations allowed) ----------------
__device__ float4 g_sorted[BB * NN];        // 26-grid sorted, w = idx bits
__device__ float4 g_fsorted[BB * NN];       // 8-grid sorted for FPS, w = idx
__device__ int    g_cellCnt[BB * NCELL];
__device__ int    g_cellStart[BB * (NCELL + 1)];
__device__ int    g_cellOfs[BB * NCELL];
__device__ int    g_ccnt[BB * CGC];
__device__ int    g_cofs[BB * CGC];
__device__ float4 g_fps[BB * NPOINT];       // FPS-selected coordinates
__device__ double g_acc[8];                 // [0..4] uniform sums, [5] repulsion
__device__ int    g_ticket;

struct UParams {
    float  r2[5];
    float  el[5];
    float  elden[5];
    int    ns[5];
    double wmul[5];
};

// exact f32 squared distance, NO fma contraction (matches XLA f32 eval)
__device__ __forceinline__ float sqdist(float ax, float ay, float az,
                                        float bx, float by, float bz) {
    float dx = __fadd_rn(ax, -bx);
    float dy = __fadd_rn(ay, -by);
    float dz = __fadd_rn(az, -bz);
    return __fadd_rn(__fadd_rn(__fmul_rn(dx, dx), __fmul_rn(dy, dy)),
                     __fmul_rn(dz, dz));
}

__device__ __forceinline__ void cellOf(float x, float y, float z,
                                       int& ix, int& iy, int& iz) {
    ix = min(GRID - 1, max(0, (int)floorf((x + 1.0f) * (0.5f * GRID))));
    iy = min(GRID - 1, max(0, (int)floorf((y + 1.0f) * (0.5f * GRID))));
    iz = min(GRID - 1, max(0, (int)floorf((z + 1.0f) * (0.5f * GRID))));
}
__device__ __forceinline__ int cellIdx(int ix, int iy, int iz) {
    return (ix * GRID + iy) * GRID + iz;
}
__device__ __forceinline__ int ccellOf(float x, float y, float z) {
    int ix = min(CG - 1, max(0, (int)floorf((x + 1.0f) * (0.5f * CG))));
    int iy = min(CG - 1, max(0, (int)floorf((y + 1.0f) * (0.5f * CG))));
    int iz = min(CG - 1, max(0, (int)floorf((z + 1.0f) * (0.5f * CG))));
    return (ix * CG + iy) * CG + iz;
}

// ---- packed f32x2 helpers (Blackwell) — per-half IEEE f32 add/mul exact ----
__device__ __forceinline__ ull pk2(float lo, float hi) {
    ull r; asm("mov.b64 %0, {%1, %2};" : "=l"(r) : "f"(lo), "f"(hi)); return r;
}
__device__ __forceinline__ void upk2(ull v, float& lo, float& hi) {
    asm("mov.b64 {%0, %1}, %2;" : "=f"(lo), "=f"(hi) : "l"(v));
}
__device__ __forceinline__ ull addx2(ull a, ull b) {
    ull r; asm("add.rn.f32x2 %0, %1, %2;" : "=l"(r) : "l"(a), "l"(b)); return r;
}
__device__ __forceinline__ ull mulx2(ull a, ull b) {
    ull r; asm("mul.rn.f32x2 %0, %1, %2;" : "=l"(r) : "l"(a), "l"(b)); return r;
}

// ================= 26-grid build (side stream: rep + uni) =================
__global__ void countKernel(const float* __restrict__ pcd) {
    int i = blockIdx.x * blockDim.x + threadIdx.x;
    if (i >= BB * NN) return;
    float x = pcd[3 * i + 0], y = pcd[3 * i + 1], z = pcd[3 * i + 2];
    int b = i >> 13;
    int ix, iy, iz; cellOf(x, y, z, ix, iy, iz);
    atomicAdd(&g_cellCnt[b * NCELL + cellIdx(ix, iy, iz)], 1);
}

__global__ __launch_bounds__(1024) void scanKernel() {
    const int b = blockIdx.x, t = threadIdx.x;
    __shared__ int s_part[1024];
    int loc[18]; int sum = 0;
    const int base = t * 18;
#pragma unroll
    for (int k = 0; k < 18; k++) {
        int c = base + k;
        int v = (c < NCELL) ? g_cellCnt[b * NCELL + c] : 0;
        loc[k] = sum; sum += v;
    }
    s_part[t] = sum;
    __syncthreads();
    for (int off = 1; off < 1024; off <<= 1) {
        int v = (t >= off) ? s_part[t - off] : 0;
        __syncthreads();
        s_part[t] += v;
        __syncthreads();
    }
    int pre = (t > 0) ? s_part[t - 1] : 0;
#pragma unroll
    for (int k = 0; k < 18; k++) {
        int c = base + k;
        if (c < NCELL) {
            int st = pre + loc[k];
            g_cellStart[b * (NCELL + 1) + c] = st;
            g_cellOfs[b * NCELL + c] = st;
        }
    }
    if (t == 0) g_cellStart[b * (NCELL + 1) + NCELL] = NN;
}

__global__ void scatterKernel(const float* __restrict__ pcd) {
    int i = blockIdx.x * blockDim.x + threadIdx.x;
    if (i >= BB * NN) return;
    float x = pcd[3 * i + 0], y = pcd[3 * i + 1], z = pcd[3 * i + 2];
    int b = i >> 13, n = i & (NN - 1);
    int ix, iy, iz; cellOf(x, y, z, ix, iy, iz);
    int pos = atomicAdd(&g_cellOfs[b * NCELL + cellIdx(ix, iy, iz)], 1);
    g_sorted[b * NN + pos] = make_float4(x, y, z, __int_as_float(n));
}

// ================= coarse 8-grid build (main stream: FPS ordering) ========
__global__ void ccountKernel(const float* __restrict__ pcd) {
    int i = blockIdx.x * blockDim.x + threadIdx.x;
    if (i >= BB * NN) return;
    float x = pcd[3 * i + 0], y = pcd[3 * i + 1], z = pcd[3 * i + 2];
    int b = i >> 13;
    atomicAdd(&g_ccnt[b * CGC + ccellOf(x, y, z)], 1);
}

__global__ __launch_bounds__(CGC) void cscanKernel() {
    const int b = blockIdx.x, t = threadIdx.x;
    __shared__ int s[CGC];
    int v = g_ccnt[b * CGC + t];
    s[t] = v;
    __syncthreads();
    for (int off = 1; off < CGC; off <<= 1) {
        int u = (t >= off) ? s[t - off] : 0;
        __syncthreads();
        s[t] += u;
        __syncthreads();
    }
    g_cofs[b * CGC + t] = s[t] - v;    // exclusive prefix
}

__global__ void cscatterKernel(const float* __restrict__ pcd) {
    int i = blockIdx.x * blockDim.x + threadIdx.x;
    if (i >= BB * NN) return;
    float x = pcd[3 * i + 0], y = pcd[3 * i + 1], z = pcd[3 * i + 2];
    int b = i >> 13, n = i & (NN - 1);
    int pos = atomicAdd(&g_cofs[b * CGC + ccellOf(x, y, z)], 1);
    g_fsorted[b * NN + pos] = make_float4(x, y, z, __int_as_float(n));
}

// ================= furthest point sampling: AABB-pruned =================
// 512 threads x 16 spatially-contiguous points (coarse-sorted). Per iteration
// each thread first tests a conservative lower bound of d^2(q, its AABB):
// if 0.98*lb >= cached max-dst, its 16 dst values provably cannot change and
// it re-submits its cached argmax candidate. dst values stay bit-identical
// to the full O(N) computation, so every selection matches the reference.
__global__ __launch_bounds__(512) void fpsKernel(const float* __restrict__ pcd) {
    extern __shared__ float s_dyn[];             // 3*NN floats (96 KB)
    float* s_x = s_dyn;
    float* s_y = s_dyn + NN;
    float* s_z = s_dyn + 2 * NN;
    __shared__ ull s_red[2][16];

    const int b = blockIdx.x, t = threadIdx.x;
    const int lane = t & 31, wid = t >> 5;
    const float4* fsrc = g_fsorted + b * NN;
    const int s0 = t * 16;

    float lx[16], ly[16], lz[16], dst[16];
    int pkc[16];
    float bnx = 1e30f, bny = 1e30f, bnz = 1e30f;
    float bxx = -1e30f, bxy = -1e30f, bxz = -1e30f;
#pragma unroll
    for (int i = 0; i < 16; i++) {
        float4 p = fsrc[s0 + i];
        lx[i] = p.x; ly[i] = p.y; lz[i] = p.z;
        s_x[s0 + i] = p.x; s_y[s0 + i] = p.y; s_z[s0 + i] = p.z;
        pkc[i] = (__float_as_int(p.w) << 13) | (s0 + i);   // (orig<<13)|slot
        dst[i] = 1e10f;
        bnx = fminf(bnx, p.x); bxx = fmaxf(bxx, p.x);
        bny = fminf(bny, p.y); bxy = fmaxf(bxy, p.y);
        bnz = fminf(bnz, p.z); bxz = fmaxf(bxz, p.z);
    }
    ull PX[8], PY[8], PZ[8];
#pragma unroll
    for (int i = 0; i < 8; i++) {
        PX[i] = pk2(lx[2 * i], lx[2 * i + 1]);
        PY[i] = pk2(ly[2 * i], ly[2 * i + 1]);
        PZ[i] = pk2(lz[2 * i], lz[2 * i + 1]);
    }
    __syncthreads();

    const float* p0 = pcd + (size_t)b * NN * 3;
    float wx = p0[0], wy = p0[1], wz = p0[2];
    if (t == 0) g_fps[b * NPOINT] = make_float4(wx, wy, wz, 0.f);

    float bv = __int_as_float(0x7f800000);   // +inf -> first iter always updates
    int bpk = 0x7FFFFFFF;

    for (int it = 1; it < NPOINT; it++) {
        // conservative lower bound on d^2 from q to this thread's AABB
        float t1x = fmaxf(fmaxf(bnx - wx, wx - bxx), 0.f);
        float t1y = fmaxf(fmaxf(bny - wy, wy - bxy), 0.f);
        float t1z = fmaxf(fmaxf(bnz - wz, wz - bxz), 0.f);
        float lb = 0.98f * (t1x * t1x + t1y * t1y + t1z * t1z);
        if (lb < bv) {
            const ull qx = pk2(-wx, -wx), qy = pk2(-wy, -wy), qz = pk2(-wz, -wz);
            float nbv = -1.f; int nbpk = 0x7FFFFFFF;
#pragma unroll
            for (int i = 0; i < 8; i++) {
                ull dx = addx2(PX[i], qx);
                ull dy = addx2(PY[i], qy);
                ull dz = addx2(PZ[i], qz);
                ull s = addx2(addx2(mulx2(dx, dx), mulx2(dy, dy)), mulx2(dz, dz));
                float d0, d1; upk2(s, d0, d1);
                float n0 = fminf(dst[2 * i], d0); dst[2 * i] = n0;
                if (n0 > nbv || (n0 == nbv && pkc[2 * i] < nbpk)) { nbv = n0; nbpk = pkc[2 * i]; }
                float n1 = fminf(dst[2 * i + 1], d1); dst[2 * i + 1] = n1;
                if (n1 > nbv || (n1 == nbv && pkc[2 * i + 1] < nbpk)) { nbv = n1; nbpk = pkc[2 * i + 1]; }
            }
            bv = nbv; bpk = nbpk;
        }
        // stage 1: warp argmax (max value, min packed orig-idx among holders)
        unsigned vb = __float_as_uint(bv);
        unsigned m  = __reduce_max_sync(0xffffffffu, vb);
        unsigned wpk = __reduce_min_sync(0xffffffffu,
                                         (vb == m) ? (unsigned)bpk : 0x7fffffffu);
        if (lane == 0) s_red[it & 1][wid] = ((ull)m << 32) | (ull)wpk;
        __syncthreads();
        // stage 2: every warp redundantly reduces the 16 partials
        ull pv = s_red[it & 1][lane & 15];
        unsigned hv = (unsigned)(pv >> 32), lv = (unsigned)pv;
        unsigned m2 = __reduce_max_sync(0xffffffffu, hv);
        unsigned w2 = __reduce_min_sync(0xffffffffu,
                                        (hv == m2) ? lv : 0x7fffffffu);
        int slot = (int)(w2 & 8191u);
        wx = s_x[slot]; wy = s_y[slot]; wz = s_z[slot];   // broadcast LDS x3
        if (t == 0) g_fps[b * NPOINT + it] = make_float4(wx, wy, wz, 0.f);
        // double-buffered s_red: one barrier per iteration is sufficient
    }
}

// ---------------- repulsion loss: grid lookup, thread per query ----------------
__global__ __launch_bounds__(256) void repKernel(float r2, float hh) {
    const int qid = blockIdx.x * 256 + threadIdx.x;
    const int lane = threadIdx.x & 31, wid = threadIdx.x >> 5;
    const int b = qid >> 13;
    const float4 q = g_sorted[qid];
    const int* cs = g_cellStart + b * (NCELL + 1);
    const float4* srt = g_sorted + b * NN;

    int cx, cy, cz; cellOf(q.x, q.y, q.z, cx, cy, cz);

    float dlist[CAPR]; int ilist[CAPR];
    int cnt = 0, minIdx = INT_MAX; float dMin = 0.f;

    for (int ix = max(0, cx - 1); ix <= min(GRID - 1, cx + 1); ix++)
    for (int iy = max(0, cy - 1); iy <= min(GRID - 1, cy + 1); iy++)
    for (int iz = max(0, cz - 1); iz <= min(GRID - 1, cz + 1); iz++) {
        int c = cellIdx(ix, iy, iz);
        int s = cs[c], e = cs[c + 1];
        for (int i = s; i < e; i++) {
            float4 p = srt[i];
            float d = sqdist(p.x, p.y, p.z, q.x, q.y, q.z);
            if (d <= r2) {
                int pi = __float_as_int(p.w);
                if (cnt < CAPR) { dlist[cnt] = d; ilist[cnt] = pi; }
                cnt++;
                if (pi < minIdx) { minIdx = pi; dMin = d; }
            }
        }
    }

    int h = min(cnt, CAPR);
    if (cnt > NSR) {  // need first-20-by-index: sort (statistically never taken)
        for (int a = 1; a < h; a++) {
            float dv = dlist[a]; int iv = ilist[a]; int k = a - 1;
            while (k >= 0 && ilist[k] > iv) {
                dlist[k + 1] = dlist[k]; ilist[k + 1] = ilist[k]; k--;
            }
            dlist[k + 1] = dv; ilist[k + 1] = iv;
        }
    }
    const int cm = min(cnt, NSR);
    float v[NSR];
#pragma unroll
    for (int i = 0; i < NSR; i++) v[i] = (i < cm) ? dlist[i] : dMin;

    double lsum = 0.0;
    for (int r = 0; r < 5; r++) {
        int mi = 0; float mv = v[0];
#pragma unroll
        for (int i = 1; i < NSR; i++) if (v[i] < mv) { mv = v[i]; mi = i; }
        if (r > 0) {
            float ds = sqrtf(mv);
            float w  = expf(-(mv / hh));
            lsum += (double)__fadd_rn(0.07f, -__fmul_rn(ds, w));
        }
        v[mi] = 3.4e38f;
    }

    for (int o = 16; o > 0; o >>= 1)
        lsum += __shfl_down_sync(0xffffffffu, lsum, o);
    __shared__ double s_bsum[8];
    if (lane == 0) s_bsum[wid] = lsum;
    __syncthreads();
    if (threadIdx.x == 0) {
        double tsum = 0.0;
        for (int w = 0; w < 8; w++) tsum += s_bsum[w];
        atomicAdd(&g_acc[5], tsum);
    }
}

// -------- uniform loss: grid lookup, warp per FPS query; fused finalize -------
__global__ __launch_bounds__(256) void uniKernel(UParams P, float* __restrict__ out) {
    __shared__ float s_hx[8][CAPU], s_hy[8][CAPU], s_hz[8][CAPU], s_hd[8][CAPU];
    __shared__ int   s_hi[8][CAPU];
    __shared__ int   s_cnt[8];

    const int wid = threadIdx.x >> 5, lane = threadIdx.x & 31;
    const int qi = blockIdx.x * 8 + wid;
    if (qi < BB * NPOINT) {
        const int b = qi / NPOINT;
        const float4 q = g_fps[qi];
        const int* cs = g_cellStart + b * (NCELL + 1);
        const float4* srt = g_sorted + b * NN;
        const float maxr2 = P.r2[4];

        if (lane == 0) s_cnt[wid] = 0;
        __syncwarp();

        int cx, cy, cz; cellOf(q.x, q.y, q.z, cx, cy, cz);
        for (int o = lane; o < 125; o += 32) {
            int dzo = o / 25 - 2, dyo = (o / 5) % 5 - 2, dxo = o % 5 - 2;
            int ix = cx + dxo, iy = cy + dyo, iz = cz + dzo;
            if (ix < 0 || ix >= GRID || iy < 0 || iy >= GRID || iz < 0 || iz >= GRID)
                continue;
            int c = cellIdx(ix, iy, iz);
            int s = cs[c], e = cs[c + 1];
            for (int i = s; i < e; i++) {
                float4 p = srt[i];
                float d = sqdist(p.x, p.y, p.z, q.x, q.y, q.z);
                if (d <= maxr2) {
                    int pos = atomicAdd(&s_cnt[wid], 1);
                    if (pos < CAPU) {
                        s_hx[wid][pos] = p.x; s_hy[wid][pos] = p.y;
                        s_hz[wid][pos] = p.z; s_hd[wid][pos] = d;
                        s_hi[wid][pos] = __float_as_int(p.w);
                    }
                }
            }
        }
        __syncwarp();
        const int h = min(s_cnt[wid], CAPU);

        for (int r = 0; r < 5; r++) {
            const float r2 = P.r2[r];
            const float el = P.el[r], elden = P.elden[r];
            int cntr = 0; unsigned cand = 0xffffffffu;
            for (int j = lane; j < h; j += 32) {
                if (s_hd[wid][j] <= r2) {
                    cntr++;
                    cand = min(cand, (unsigned)s_hi[wid][j]);
                }
            }
            cntr = __reduce_add_sync(0xffffffffu, cntr);
            unsigned minI = __reduce_min_sync(0xffffffffu, cand);

            double lsum = 0.0;
            for (int j = lane; j < h; j += 32) {
                if (s_hd[wid][j] <= r2 && (unsigned)s_hi[wid][j] != minI) {
                    float xj = s_hx[wid][j], yj = s_hy[wid][j], zj = s_hz[wid][j];
                    float mn = 3.4e38f;
                    for (int k = 0; k < h; k++) {
                        if (k == j || s_hd[wid][k] > r2) continue;
                        float d = sqdist(xj, yj, zj,
                                         s_hx[wid][k], s_hy[wid][k], s_hz[wid][k]);
                        mn = fminf(mn, d);
                    }
                    float s  = sqrtf(__fadd_rn(mn, 1e-8f));
                    float tt = __fadd_rn(s, -el);
                    lsum += (double)(__fmul_rn(tt, tt) / elden);
                }
            }
            for (int o = 16; o > 0; o >>= 1)
                lsum += __shfl_down_sync(0xffffffffu, lsum, o);
            if (lane == 0) {
                float s0 = sqrtf(1e-8f);
                float t0 = __fadd_rn(s0, -el);
                float f0 = __fmul_rn(t0, t0) / elden;
                lsum += (double)f0 * (double)(P.ns[r] - cntr + 1);
                atomicAdd(&g_acc[r], lsum);
            }
        }
        if (lane == 0) __threadfence();
    }
    __syncthreads();
    if (threadIdx.x == 0) {
        int tk = atomicAdd(&g_ticket, 1);
        if (tk == (int)gridDim.x - 1) {
            __threadfence();
            double u = 0.0;
            for (int r = 0; r < 5; r++) {
                double mean_r = g_acc[r] / ((double)BB * NPOINT * P.ns[r]);
                u += mean_r * P.wmul[r];
            }
            u /= 5.0;
            double rep = g_acc[5] / ((double)BB * NN * 4.0);
            out[0] = (float)u;
            out[1] = (float)rep;
        }
    }
}

// ---------------- host launcher ----------------
extern "C" void kernel_launch(void* const* d_in, const int* in_sizes, int n_in,
                              void* d_out, int out_size) {
    (void)in_sizes; (void)n_in; (void)out_size;
    const float* pcd = (const float*)d_in[0];
    float* out = (float*)d_out;

    UParams P;
    const double pct[5] = {0.004, 0.008, 0.01, 0.012, 0.016};
    const double PI = 3.141592653589793;
    for (int r = 0; r < 5; r++) {
        int ns = (int)((double)NN * pct[r]);
        double rr = sqrt(pct[r] * 1.0);
        double disk = PI * 1.0 * pct[r] / (double)ns;
        double el = sqrt(2.0 * disk / 1.732);
        P.r2[r]    = (float)(rr * rr);
        P.el[r]    = (float)el;
        P.elden[r] = (float)(el + 1e-8);
        P.ns[r]    = ns;
        P.wmul[r]  = (pct[r] * 100.0) * (pct[r] * 100.0);
    }

    const int FPS_SMEM = NN * 3 * (int)sizeof(float);   // 96 KB
    cudaFuncSetAttribute(fpsKernel,
                         cudaFuncAttributeMaxDynamicSharedMemorySize, FPS_SMEM);

    void* pCnt = nullptr; void* pAcc = nullptr; void* pTick = nullptr; void* pCC = nullptr;
    cudaGetSymbolAddress(&pCnt, g_cellCnt);
    cudaGetSymbolAddress(&pAcc, g_acc);
    cudaGetSymbolAddress(&pTick, g_ticket);
    cudaGetSymbolAddress(&pCC, g_ccnt);

    cudaStream_t s1;
    cudaEvent_t eA, eB;
    cudaStreamCreate(&s1);
    cudaEventCreateWithFlags(&eA, cudaEventDisableTiming);
    cudaEventCreateWithFlags(&eB, cudaEventDisableTiming);

    cudaEventRecord(eA, 0);
    cudaStreamWaitEvent(s1, eA, 0);

    // side stream: 26-grid build + repulsion (overlaps FPS entirely)
    cudaMemsetAsync(pCnt, 0, sizeof(int) * BB * NCELL, s1);
    cudaMemsetAsync(pAcc, 0, sizeof(double) * 8, s1);
    cudaMemsetAsync(pTick, 0, sizeof(int), s1);
    countKernel<<<(BB * NN + 255) / 256, 256, 0, s1>>>(pcd);
    scanKernel<<<BB, 1024, 0, s1>>>();
    scatterKernel<<<(BB * NN + 255) / 256, 256, 0, s1>>>(pcd);
    repKernel<<<(BB * NN) / 256, 256, 0, s1>>>((float)(0.07 * 0.07),
                                               (float)(0.03 * 0.03));
    cudaEventRecord(eB, s1);

    // main stream: coarse 8-grid sort, then AABB-pruned FPS
    cudaMemsetAsync(pCC, 0, sizeof(int) * BB * CGC, 0);
    ccountKernel<<<(BB * NN + 255) / 256, 256>>>(pcd);
    cscanKernel<<<BB, CGC>>>();
    cscatterKernel<<<(BB * NN + 255) / 256, 256>>>(pcd);
    fpsKernel<<<BB, 512, FPS_SMEM>>>(pcd);

    cudaStreamWaitEvent(0, eB, 0);
    uniKernel<<<(BB * NPOINT + 7) / 8, 256>>>(P, out);
}

// round 13
// speedup vs baseline: 1.3794x; 1.3794x over previous
#include <cuda_runtime.h>
#include <math.h>
#include <limits.h>

#define BB 4
#define NN 8192
#define NPOINT 409        // int(8192 * 0.05)
#define NSR 20            // repulsion nsample
#define GRID 26
#define NCELL (GRID*GRID*GRID)   // 17576
#define CAPR 24
#define CAPU 48
#define CG 8
#define CGC (CG*CG*CG)    // 512 coarse cells (FPS in-kernel ordering)

typedef unsigned long long ull;

// ---------------- device scratch (no allocations allowed) ----------------
__device__ float4 g_sorted[BB * NN];        // cell-sorted points, w = idx bits
__device__ int    g_cellCnt[BB * NCELL];
__device__ int    g_cellStart[BB * (NCELL + 1)];
__device__ int    g_cellOfs[BB * NCELL];
__device__ float4 g_fps[BB * NPOINT];       // FPS-selected coordinates
__device__ double g_acc[8];                 // [0..4] uniform sums, [5] repulsion
__device__ int    g_ticket;

struct UParams {
    float  r2[5];
    float  el[5];
    float  elden[5];
    int    ns[5];
    double wmul[5];
};

// exact f32 squared distance, NO fma contraction (matches XLA f32 eval)
__device__ __forceinline__ float sqdist(float ax, float ay, float az,
                                        float bx, float by, float bz) {
    float dx = __fadd_rn(ax, -bx);
    float dy = __fadd_rn(ay, -by);
    float dz = __fadd_rn(az, -bz);
    return __fadd_rn(__fadd_rn(__fmul_rn(dx, dx), __fmul_rn(dy, dy)),
                     __fmul_rn(dz, dz));
}

__device__ __forceinline__ void cellOf(float x, float y, float z,
                                       int& ix, int& iy, int& iz) {
    ix = min(GRID - 1, max(0, (int)floorf((x + 1.0f) * (0.5f * GRID))));
    iy = min(GRID - 1, max(0, (int)floorf((y + 1.0f) * (0.5f * GRID))));
    iz = min(GRID - 1, max(0, (int)floorf((z + 1.0f) * (0.5f * GRID))));
}
__device__ __forceinline__ int cellIdx(int ix, int iy, int iz) {
    return (ix * GRID + iy) * GRID + iz;
}

// Morton-ordered coarse cell (compact 3D locality for warp AABBs)
__device__ __forceinline__ int mortonCellOf(float x, float y, float z) {
    int ix = min(CG - 1, max(0, (int)floorf((x + 1.0f) * (0.5f * CG))));
    int iy = min(CG - 1, max(0, (int)floorf((y + 1.0f) * (0.5f * CG))));
    int iz = min(CG - 1, max(0, (int)floorf((z + 1.0f) * (0.5f * CG))));
    int m = 0;
#pragma unroll
    for (int b = 0; b < 3; b++) {
        m |= ((ix >> b) & 1) << (3 * b + 2);
        m |= ((iy >> b) & 1) << (3 * b + 1);
        m |= ((iz >> b) & 1) << (3 * b + 0);
    }
    return m;
}

// ---- packed f32x2 helpers (Blackwell) — per-half IEEE f32 add/mul exact ----
__device__ __forceinline__ ull pk2(float lo, float hi) {
    ull r; asm("mov.b64 %0, {%1, %2};" : "=l"(r) : "f"(lo), "f"(hi)); return r;
}
__device__ __forceinline__ void upk2(ull v, float& lo, float& hi) {
    asm("mov.b64 {%0, %1}, %2;" : "=f"(lo), "=f"(hi) : "l"(v));
}
__device__ __forceinline__ ull addx2(ull a, ull b) {
    ull r; asm("add.rn.f32x2 %0, %1, %2;" : "=l"(r) : "l"(a), "l"(b)); return r;
}
__device__ __forceinline__ ull mulx2(ull a, ull b) {
    ull r; asm("mul.rn.f32x2 %0, %1, %2;" : "=l"(r) : "l"(a), "l"(b)); return r;
}

// ---------------- count grid cells (side stream) ----------------
__global__ void countKernel(const float* __restrict__ pcd) {
    int i = blockIdx.x * blockDim.x + threadIdx.x;
    if (i >= BB * NN) return;
    float x = pcd[3 * i + 0], y = pcd[3 * i + 1], z = pcd[3 * i + 2];
    int b = i >> 13;
    int ix, iy, iz; cellOf(x, y, z, ix, iy, iz);
    atomicAdd(&g_cellCnt[b * NCELL + cellIdx(ix, iy, iz)], 1);
}

// ---------------- exclusive scan per batch (one block) ----------------
__global__ __launch_bounds__(1024) void scanKernel() {
    const int b = blockIdx.x, t = threadIdx.x;
    __shared__ int s_part[1024];
    int loc[18]; int sum = 0;
    const int base = t * 18;
#pragma unroll
    for (int k = 0; k < 18; k++) {
        int c = base + k;
        int v = (c < NCELL) ? g_cellCnt[b * NCELL + c] : 0;
        loc[k] = sum; sum += v;
    }
    s_part[t] = sum;
    __syncthreads();
    for (int off = 1; off < 1024; off <<= 1) {
        int v = (t >= off) ? s_part[t - off] : 0;
        __syncthreads();
        s_part[t] += v;
        __syncthreads();
    }
    int pre = (t > 0) ? s_part[t - 1] : 0;
#pragma unroll
    for (int k = 0; k < 18; k++) {
        int c = base + k;
        if (c < NCELL) {
            int st = pre + loc[k];
            g_cellStart[b * (NCELL + 1) + c] = st;
            g_cellOfs[b * NCELL + c] = st;
        }
    }
    if (t == 0) g_cellStart[b * (NCELL + 1) + NCELL] = NN;
}

// ---------------- scatter into sorted order ----------------
__global__ void scatterKernel(const float* __restrict__ pcd) {
    int i = blockIdx.x * blockDim.x + threadIdx.x;
    if (i >= BB * NN) return;
    float x = pcd[3 * i + 0], y = pcd[3 * i + 1], z = pcd[3 * i + 2];
    int b = i >> 13, n = i & (NN - 1);
    int ix, iy, iz; cellOf(x, y, z, ix, iy, iz);
    int pos = atomicAdd(&g_cellOfs[b * NCELL + cellIdx(ix, iy, iz)], 1);
    g_sorted[b * NN + pos] = make_float4(x, y, z, __int_as_float(n));
}

// ---------------- furthest point sampling: one block per batch ----------------
// In-kernel Morton binning (smem count/scan/scatter, ~7us) gives each warp 256
// spatially-compact points. Per iteration a warp-uniform AABB bound proves the
// warp's 256 fmin updates are no-ops and re-submits its cached (max, argmax);
// the dst state stays bit-identical to the full O(N) recurrence. Update path
// is the proven round-9 inner loop. One barrier/iter, double-buffered partials.
__global__ __launch_bounds__(1024) void fpsKernel(const float* __restrict__ pcd) {
    extern __shared__ float4 s_B[];              // 8192 float4 = 128 KB
    __shared__ int s_cnt[CGC];
    __shared__ int s_sc[CGC];
    __shared__ ull s_red[2][32];

    const int b = blockIdx.x, t = threadIdx.x;
    const int lane = t & 31, wid = t >> 5;
    const float* src = pcd + (size_t)b * NN * 3;

    // ---- in-kernel coarse binning ----
    if (t < CGC) s_cnt[t] = 0;
    __syncthreads();

    float px[8], py[8], pz[8]; int cv[8];
#pragma unroll
    for (int k = 0; k < 8; k++) {
        int i = t + 1024 * k;
        px[k] = src[3 * i]; py[k] = src[3 * i + 1]; pz[k] = src[3 * i + 2];
        cv[k] = mortonCellOf(px[k], py[k], pz[k]);
        atomicAdd(&s_cnt[cv[k]], 1);
    }
    __syncthreads();
    if (t < CGC) s_sc[t] = s_cnt[t];
    __syncthreads();
    for (int off = 1; off < CGC; off <<= 1) {
        int add = 0;
        if (t < CGC && t >= off) add = s_sc[t - off];
        __syncthreads();
        if (t < CGC) s_sc[t] += add;
        __syncthreads();
    }
    if (t < CGC) s_cnt[t] = s_sc[t] - s_cnt[t];   // exclusive start cursor
    __syncthreads();
#pragma unroll
    for (int k = 0; k < 8; k++) {
        int pos = atomicAdd(&s_cnt[cv[k]], 1);
        s_B[pos] = make_float4(px[k], py[k], pz[k], 0.f);
    }
    __syncthreads();

    // ---- load own 8 contiguous slots + bbox ----
    const int s0 = 8 * t;
    ull PX[4], PY[4], PZ[4];
    float dst[8];
    float bnx = 1e30f, bny = 1e30f, bnz = 1e30f;
    float bxx = -1e30f, bxy = -1e30f, bxz = -1e30f;
#pragma unroll
    for (int k = 0; k < 8; k++) {
        float4 p = s_B[s0 + k];
        px[k] = p.x; py[k] = p.y; pz[k] = p.z;
        dst[k] = 1e10f;
        bnx = fminf(bnx, p.x); bxx = fmaxf(bxx, p.x);
        bny = fminf(bny, p.y); bxy = fmaxf(bxy, p.y);
        bnz = fminf(bnz, p.z); bxz = fmaxf(bxz, p.z);
    }
#pragma unroll
    for (int g = 0; g < 4; g++) {
        PX[g] = pk2(px[2 * g], px[2 * g + 1]);
        PY[g] = pk2(py[2 * g], py[2 * g + 1]);
        PZ[g] = pk2(pz[2 * g], pz[2 * g + 1]);
    }
    // warp bbox (all lanes end with identical values)
#pragma unroll
    for (int o = 16; o > 0; o >>= 1) {
        bnx = fminf(bnx, __shfl_xor_sync(0xffffffffu, bnx, o));
        bny = fminf(bny, __shfl_xor_sync(0xffffffffu, bny, o));
        bnz = fminf(bnz, __shfl_xor_sync(0xffffffffu, bnz, o));
        bxx = fmaxf(bxx, __shfl_xor_sync(0xffffffffu, bxx, o));
        bxy = fmaxf(bxy, __shfl_xor_sync(0xffffffffu, bxy, o));
        bxz = fmaxf(bxz, __shfl_xor_sync(0xffffffffu, bxz, o));
    }

    // first sample = original point 0
    float wx = src[0], wy = src[1], wz = src[2];
    if (t == 0) g_fps[b * NPOINT] = make_float4(wx, wy, wz, 0.f);

    unsigned mc = __float_as_uint(1e10f);      // cached warp max (value bits)
    unsigned wic = (unsigned)(256 * wid);      // cached argmax slot

    for (int it = 1; it < NPOINT; it++) {
        // warp-uniform conservative bound: skip iff no dst in warp can change
        float tx = fmaxf(fmaxf(bnx - wx, wx - bxx), 0.f);
        float ty = fmaxf(fmaxf(bny - wy, wy - bxy), 0.f);
        float tz = fmaxf(fmaxf(bnz - wz, wz - bxz), 0.f);
        float lb = 0.98f * (tx * tx + ty * ty + tz * tz);
        if (lb < __uint_as_float(mc)) {
            const ull qx = pk2(-wx, -wx), qy = pk2(-wy, -wy), qz = pk2(-wz, -wz);
            float nbv = -1.f; unsigned nbi = 0u;
#pragma unroll
            for (int g = 0; g < 4; g++) {
                ull dx = addx2(PX[g], qx);
                ull dy = addx2(PY[g], qy);
                ull dz = addx2(PZ[g], qz);
                ull s = addx2(addx2(mulx2(dx, dx), mulx2(dy, dy)), mulx2(dz, dz));
                float d0, d1; upk2(s, d0, d1);
                float n0 = fminf(dst[2 * g], d0); dst[2 * g] = n0;
                if (n0 > nbv) { nbv = n0; nbi = (unsigned)(s0 + 2 * g); }
                float n1 = fminf(dst[2 * g + 1], d1); dst[2 * g + 1] = n1;
                if (n1 > nbv) { nbv = n1; nbi = (unsigned)(s0 + 2 * g + 1); }
            }
            unsigned vb = __float_as_uint(nbv);
            unsigned m  = __reduce_max_sync(0xffffffffu, vb);
            unsigned wi = __reduce_min_sync(0xffffffffu,
                                            (vb == m) ? nbi : 0xffffffffu);
            mc = m; wic = wi;
        }
        if (lane == 0) s_red[it & 1][wid] = ((ull)mc << 32) | (ull)wic;
        __syncthreads();
        // stage 2: every warp redundantly reduces the 32 partials
        ull pv = s_red[it & 1][lane];
        unsigned hv = (unsigned)(pv >> 32), lv = (unsigned)pv;
        unsigned m2 = __reduce_max_sync(0xffffffffu, hv);
        unsigned w2 = __reduce_min_sync(0xffffffffu,
                                        (hv == m2) ? lv : 0xffffffffu);
        float4 p = s_B[w2];                    // broadcast LDS.128
        wx = p.x; wy = p.y; wz = p.z;
        if (t == 0) g_fps[b * NPOINT + it] = make_float4(wx, wy, wz, 0.f);
        // double-buffered s_red: one barrier per iteration suffices
    }
}

// ---------------- repulsion loss: grid lookup, thread per query ----------------
__global__ __launch_bounds__(256) void repKernel(float r2, float hh) {
    const int qid = blockIdx.x * 256 + threadIdx.x;
    const int lane = threadIdx.x & 31, wid = threadIdx.x >> 5;
    const int b = qid >> 13;
    const float4 q = g_sorted[qid];
    const int* cs = g_cellStart + b * (NCELL + 1);
    const float4* srt = g_sorted + b * NN;

    int cx, cy, cz; cellOf(q.x, q.y, q.z, cx, cy, cz);

    float dlist[CAPR]; int ilist[CAPR];
    int cnt = 0, minIdx = INT_MAX; float dMin = 0.f;

    for (int ix = max(0, cx - 1); ix <= min(GRID - 1, cx + 1); ix++)
    for (int iy = max(0, cy - 1); iy <= min(GRID - 1, cy + 1); iy++)
    for (int iz = max(0, cz - 1); iz <= min(GRID - 1, cz + 1); iz++) {
        int c = cellIdx(ix, iy, iz);
        int s = cs[c], e = cs[c + 1];
        for (int i = s; i < e; i++) {
            float4 p = srt[i];
            float d = sqdist(p.x, p.y, p.z, q.x, q.y, q.z);
            if (d <= r2) {
                int pi = __float_as_int(p.w);
                if (cnt < CAPR) { dlist[cnt] = d; ilist[cnt] = pi; }
                cnt++;
                if (pi < minIdx) { minIdx = pi; dMin = d; }
            }
        }
    }

    int h = min(cnt, CAPR);
    if (cnt > NSR) {  // need first-20-by-index: sort (statistically never taken)
        for (int a = 1; a < h; a++) {
            float dv = dlist[a]; int iv = ilist[a]; int k = a - 1;
            while (k >= 0 && ilist[k] > iv) {
                dlist[k + 1] = dlist[k]; ilist[k + 1] = ilist[k]; k--;
            }
            dlist[k + 1] = dv; ilist[k + 1] = iv;
        }
    }
    const int cm = min(cnt, NSR);
    float v[NSR];
#pragma unroll
    for (int i = 0; i < NSR; i++) v[i] = (i < cm) ? dlist[i] : dMin;

    double lsum = 0.0;
    for (int r = 0; r < 5; r++) {
        int mi = 0; float mv = v[0];
#pragma unroll
        for (int i = 1; i < NSR; i++) if (v[i] < mv) { mv = v[i]; mi = i; }
        if (r > 0) {
            float ds = sqrtf(mv);
            float w  = expf(-(mv / hh));
            lsum += (double)__fadd_rn(0.07f, -__fmul_rn(ds, w));
        }
        v[mi] = 3.4e38f;
    }

    for (int o = 16; o > 0; o >>= 1)
        lsum += __shfl_down_sync(0xffffffffu, lsum, o);
    __shared__ double s_bsum[8];
    if (lane == 0) s_bsum[wid] = lsum;
    __syncthreads();
    if (threadIdx.x == 0) {
        double tsum = 0.0;
        for (int w = 0; w < 8; w++) tsum += s_bsum[w];
        atomicAdd(&g_acc[5], tsum);
    }
}

// -------- uniform loss: grid lookup, warp per FPS query; fused finalize -------
__global__ __launch_bounds__(256) void uniKernel(UParams P, float* __restrict__ out) {
    __shared__ float s_hx[8][CAPU], s_hy[8][CAPU], s_hz[8][CAPU], s_hd[8][CAPU];
    __shared__ int   s_hi[8][CAPU];
    __shared__ int   s_cnt[8];

    const int wid = threadIdx.x >> 5, lane = threadIdx.x & 31;
    const int qi = blockIdx.x * 8 + wid;
    if (qi < BB * NPOINT) {
        const int b = qi / NPOINT;
        const float4 q = g_fps[qi];
        const int* cs = g_cellStart + b * (NCELL + 1);
        const float4* srt = g_sorted + b * NN;
        const float maxr2 = P.r2[4];

        if (lane == 0) s_cnt[wid] = 0;
        __syncwarp();

        int cx, cy, cz; cellOf(q.x, q.y, q.z, cx, cy, cz);
        for (int o = lane; o < 125; o += 32) {
            int dzo = o / 25 - 2, dyo = (o / 5) % 5 - 2, dxo = o % 5 - 2;
            int ix = cx + dxo, iy = cy + dyo, iz = cz + dzo;
            if (ix < 0 || ix >= GRID || iy < 0 || iy >= GRID || iz < 0 || iz >= GRID)
                continue;
            int c = cellIdx(ix, iy, iz);
            int s = cs[c], e = cs[c + 1];
            for (int i = s; i < e; i++) {
                float4 p = srt[i];
                float d = sqdist(p.x, p.y, p.z, q.x, q.y, q.z);
                if (d <= maxr2) {
                    int pos = atomicAdd(&s_cnt[wid], 1);
                    if (pos < CAPU) {
                        s_hx[wid][pos] = p.x; s_hy[wid][pos] = p.y;
                        s_hz[wid][pos] = p.z; s_hd[wid][pos] = d;
                        s_hi[wid][pos] = __float_as_int(p.w);
                    }
                }
            }
        }
        __syncwarp();
        const int h = min(s_cnt[wid], CAPU);

        for (int r = 0; r < 5; r++) {
            const float r2 = P.r2[r];
            const float el = P.el[r], elden = P.elden[r];
            int cntr = 0; unsigned cand = 0xffffffffu;
            for (int j = lane; j < h; j += 32) {
                if (s_hd[wid][j] <= r2) {
                    cntr++;
                    cand = min(cand, (unsigned)s_hi[wid][j]);
                }
            }
            cntr = __reduce_add_sync(0xffffffffu, cntr);
            unsigned minI = __reduce_min_sync(0xffffffffu, cand);

            double lsum = 0.0;
            for (int j = lane; j < h; j += 32) {
                if (s_hd[wid][j] <= r2 && (unsigned)s_hi[wid][j] != minI) {
                    float xj = s_hx[wid][j], yj = s_hy[wid][j], zj = s_hz[wid][j];
                    float mn = 3.4e38f;
                    for (int k = 0; k < h; k++) {
                        if (k == j || s_hd[wid][k] > r2) continue;
                        float d = sqdist(xj, yj, zj,
                                         s_hx[wid][k], s_hy[wid][k], s_hz[wid][k]);
                        mn = fminf(mn, d);
                    }
                    float s  = sqrtf(__fadd_rn(mn, 1e-8f));
                    float tt = __fadd_rn(s, -el);
                    lsum += (double)(__fmul_rn(tt, tt) / elden);
                }
            }
            for (int o = 16; o > 0; o >>= 1)
                lsum += __shfl_down_sync(0xffffffffu, lsum, o);
            if (lane == 0) {
                float s0 = sqrtf(1e-8f);
                float t0 = __fadd_rn(s0, -el);
                float f0 = __fmul_rn(t0, t0) / elden;
                lsum += (double)f0 * (double)(P.ns[r] - cntr + 1);
                atomicAdd(&g_acc[r], lsum);
            }
        }
        if (lane == 0) __threadfence();
    }
    __syncthreads();
    if (threadIdx.x == 0) {
        int tk = atomicAdd(&g_ticket, 1);
        if (tk == (int)gridDim.x - 1) {   // last block: finalize
            __threadfence();
            double u = 0.0;
            for (int r = 0; r < 5; r++) {
                double mean_r = g_acc[r] / ((double)BB * NPOINT * P.ns[r]);
                u += mean_r * P.wmul[r];
            }
            u /= 5.0;
            double rep = g_acc[5] / ((double)BB * NN * 4.0);
            out[0] = (float)u;
            out[1] = (float)rep;
        }
    }
}

// ---------------- host launcher ----------------
extern "C" void kernel_launch(void* const* d_in, const int* in_sizes, int n_in,
                              void* d_out, int out_size) {
    (void)in_sizes; (void)n_in; (void)out_size;
    const float* pcd = (const float*)d_in[0];
    float* out = (float*)d_out;

    UParams P;
    const double pct[5] = {0.004, 0.008, 0.01, 0.012, 0.016};
    const double PI = 3.141592653589793;
    for (int r = 0; r < 5; r++) {
        int ns = (int)((double)NN * pct[r]);
        double rr = sqrt(pct[r] * 1.0);
        double disk = PI * 1.0 * pct[r] / (double)ns;
        double el = sqrt(2.0 * disk / 1.732);
        P.r2[r]    = (float)(rr * rr);
        P.el[r]    = (float)el;
        P.elden[r] = (float)(el + 1e-8);
        P.ns[r]    = ns;
        P.wmul[r]  = (pct[r] * 100.0) * (pct[r] * 100.0);
    }

    const int FPS_SMEM = NN * (int)sizeof(float4);   // 128 KB sorted table
    cudaFuncSetAttribute(fpsKernel,
                         cudaFuncAttributeMaxDynamicSharedMemorySize, FPS_SMEM);

    void* pCnt = nullptr; void* pAcc = nullptr; void* pTick = nullptr;
    cudaGetSymbolAddress(&pCnt, g_cellCnt);
    cudaGetSymbolAddress(&pAcc, g_acc);
    cudaGetSymbolAddress(&pTick, g_ticket);

    // fork a side stream at capture origin: grid build + repulsion overlap FPS
    // (which occupies only 4 SMs and starts immediately). No cross-kernel
    // spin-waits anywhere — join via event before uniKernel.
    cudaStream_t s1;
    cudaEvent_t eA, eB;
    cudaStreamCreate(&s1);
    cudaEventCreateWithFlags(&eA, cudaEventDisableTiming);
    cudaEventCreateWithFlags(&eB, cudaEventDisableTiming);

    cudaEventRecord(eA, 0);
    cudaStreamWaitEvent(s1, eA, 0);

    // side stream: zero scratch, grid build, repulsion
    cudaMemsetAsync(pCnt, 0, sizeof(int) * BB * NCELL, s1);
    cudaMemsetAsync(pAcc, 0, sizeof(double) * 8, s1);
    cudaMemsetAsync(pTick, 0, sizeof(int), s1);
    countKernel<<<(BB * NN + 255) / 256, 256, 0, s1>>>(pcd);
    scanKernel<<<BB, 1024, 0, s1>>>();
    scatterKernel<<<(BB * NN + 255) / 256, 256, 0, s1>>>(pcd);
    repKernel<<<(BB * NN) / 256, 256, 0, s1>>>((float)(0.07 * 0.07),
                                               (float)(0.03 * 0.03));
    cudaEventRecord(eB, s1);

    // main stream: FPS starts immediately
    fpsKernel<<<BB, 1024, FPS_SMEM>>>(pcd);

    cudaStreamWaitEvent(0, eB, 0);
    uniKernel<<<(BB * NPOINT + 7) / 8, 256>>>(P, out);   // finalize fused
}